// round 16
// baseline (speedup 1.0000x reference)
#include <cuda_runtime.h>
#include <cuda_bf16.h>
#include <cstdint>

#define BATCH 4
#define NQ 20
#define DIM (1u << NQ)

__device__ float2 g_state[BATCH * DIM];                 // 32 MB (kA -> kB)
__device__ __nv_bfloat162 g_Gh[(size_t)BATCH * 1024 * 1024];  // 16 MB: bf16-hi of G (K=2048)
__device__ __nv_bfloat162 g_Gl[(size_t)BATCH * 1024 * 1024];  // 16 MB: residual lo
__device__ __nv_bfloat162 g_Hh[(size_t)BATCH * 1024 * 1024];  // 16 MB: H-hi = (im,-re) of Gh
__device__ __nv_bfloat162 g_Hl[(size_t)BATCH * 1024 * 1024];  // 16 MB: H-lo

__device__ float2 d_F[19][16];   // fused 4x4 chain gates (row-major, i=2*s_q+s_{q+1})

// ---------------------------------------------------------------------------
// helpers
// ---------------------------------------------------------------------------
__device__ __forceinline__ uint32_t smem_u32(const void* p) {
    uint32_t a;
    asm("{ .reg .u64 t; cvta.to.shared.u64 t, %1; cvt.u32.u64 %0, t; }" : "=r"(a) : "l"(p));
    return a;
}
__device__ __forceinline__ void cpa16(uint32_t dst, const void* src) {
    asm volatile("cp.async.cg.shared.global [%0], [%1], 16;" :: "r"(dst), "l"(src));
}
#define CP_COMMIT() asm volatile("cp.async.commit_group;" ::: "memory")
#define CP_WAIT0()  asm volatile("cp.async.wait_group 0;" ::: "memory")
#define CP_WAIT1()  asm volatile("cp.async.wait_group 1;" ::: "memory")

#define LDM4(r, addr) \
    asm volatile("ldmatrix.sync.aligned.m8n8.x4.shared.b16 {%0,%1,%2,%3}, [%4];" \
        : "=r"((r)[0]), "=r"((r)[1]), "=r"((r)[2]), "=r"((r)[3]) : "r"(addr))

#define MMA(d, a, b0, b1) \
    asm volatile("mma.sync.aligned.m16n8k16.row.col.f32.bf16.bf16.f32 " \
        "{%0,%1,%2,%3}, {%4,%5,%6,%7}, {%8,%9}, {%0,%1,%2,%3};" \
        : "+f"((d)[0]), "+f"((d)[1]), "+f"((d)[2]), "+f"((d)[3]) \
        : "r"((a)[0]), "r"((a)[1]), "r"((a)[2]), "r"((a)[3]), "r"(b0), "r"(b1))

// ---------------------------------------------------------------------------
// Gate precompute: fuse ALL singles into the 19 chain gates (fp64).
//   F(q,q+1) = (U2(q) (x) Q) * C(q,q+1) * (R (x) U1(q+1))
//   R = U1(0) for q==0 else I ;  Q = U2(19) for q==18 else I
// ---------------------------------------------------------------------------
struct cd { double re, im; };
__device__ __forceinline__ cd cmuld(cd a, cd b) {
    return {a.re * b.re - a.im * b.im, a.re * b.im + a.im * b.re};
}
__device__ __forceinline__ cd caddd(cd a, cd b) { return {a.re + b.re, a.im + b.im}; }
__device__ void mm2(const cd* A, const cd* B, cd* C) {
    C[0] = caddd(cmuld(A[0], B[0]), cmuld(A[1], B[2]));
    C[1] = caddd(cmuld(A[0], B[1]), cmuld(A[1], B[3]));
    C[2] = caddd(cmuld(A[2], B[0]), cmuld(A[3], B[2]));
    C[3] = caddd(cmuld(A[2], B[1]), cmuld(A[3], B[3]));
}
__device__ void mm4(const cd* A, const cd* B, cd* C) {
    for (int i = 0; i < 4; i++)
        for (int j = 0; j < 4; j++) {
            cd s = {0, 0};
            for (int k = 0; k < 4; k++) s = caddd(s, cmuld(A[i * 4 + k], B[k * 4 + j]));
            C[i * 4 + j] = s;
        }
}
__device__ void kron2(const cd* A, const cd* B, cd* K) {
    for (int i0 = 0; i0 < 2; i0++)
        for (int i1 = 0; i1 < 2; i1++)
            for (int j0 = 0; j0 < 2; j0++)
                for (int j1 = 0; j1 < 2; j1++)
                    K[(2 * i0 + i1) * 4 + (2 * j0 + j1)] =
                        cmuld(A[i0 * 2 + j0], B[i1 * 2 + j1]);
}

__global__ void kprep(const float* __restrict__ w) {
    __shared__ double sU[2][20][4][2];  // [layer][q][elem][re/im]
    int t = threadIdx.x;
    const double WM = 0.6324555320336759;  // sqrt(2)/sqrt(5)
    if (t < 40) {
        int q = t % 20;
        int layer = t < 20 ? 0 : 1;
        int base = layer == 0 ? 3 * q : (117 + 3 * q);
        double ax = (double)w[base]     * WM * 0.5;
        double ay = (double)w[base + 1] * WM * 0.5;
        double az = (double)w[base + 2] * WM * 0.5;
        double cx = cos(ax), sx = sin(ax);
        double cy = cos(ay), sy = sin(ay);
        double cz = cos(az), sz = sin(az);
        cd RX[4] = {{cx, 0}, {0, -sx}, {0, -sx}, {cx, 0}};
        cd RY[4] = {{cy, 0}, {-sy, 0}, {sy, 0}, {cy, 0}};
        cd RYX[4]; mm2(RY, RX, RYX);
        cd z0 = {cz, -sz}, z1 = {cz, sz};
        cd U[4] = {cmuld(z0, RYX[0]), cmuld(z0, RYX[1]),
                   cmuld(z1, RYX[2]), cmuld(z1, RYX[3])};
        for (int i = 0; i < 4; i++) { sU[layer][q][i][0] = U[i].re; sU[layer][q][i][1] = U[i].im; }
    }
    __syncthreads();
    if (t < 19) {
        int q = t;
        int base = 60 + 3 * q;
        double ax = (double)w[base]     * WM * 0.5;
        double ay = (double)w[base + 1] * WM * 0.5;
        double az = (double)w[base + 2] * WM * 0.5;
        double cx = cos(ax), sx = sin(ax);
        double cy = cos(ay), sy = sin(ay);
        double cz = cos(az), sz = sin(az);
        cd RXXb[4] = {{cx, 0}, {0, -sx}, {0, -sx}, {cx, 0}};
        cd RYY0[4] = {{cy, 0}, {0,  sy}, {0,  sy}, {cy, 0}};
        cd RYY1[4] = {{cy, 0}, {0, -sy}, {0, -sy}, {cy, 0}};
        cd M0[4]; mm2(RYY0, RXXb, M0);
        cd M1[4]; mm2(RYY1, RXXb, M1);
        cd p0 = {cz, -sz}, p1 = {cz, sz};
        cd g00[4], g01[4];
        for (int i = 0; i < 4; i++) { g00[i] = cmuld(p0, M0[i]); g01[i] = cmuld(p1, M1[i]); }
        cd C[16];
        for (int i = 0; i < 16; i++) C[i] = {0, 0};
        C[0 * 4 + 0] = g00[0]; C[0 * 4 + 3] = g00[1];
        C[3 * 4 + 0] = g00[2]; C[3 * 4 + 3] = g00[3];
        C[1 * 4 + 1] = g01[0]; C[1 * 4 + 2] = g01[1];
        C[2 * 4 + 1] = g01[2]; C[2 * 4 + 2] = g01[3];
        cd I2[4] = {{1, 0}, {0, 0}, {0, 0}, {1, 0}};
        cd R[4], S[4], P[4], Q[4];
        for (int i = 0; i < 4; i++) {
            R[i] = (q == 0)  ? cd{sU[0][0][i][0],  sU[0][0][i][1]}  : I2[i];
            S[i] = cd{sU[0][q + 1][i][0], sU[0][q + 1][i][1]};
            P[i] = cd{sU[1][q][i][0],     sU[1][q][i][1]};
            Q[i] = (q == 18) ? cd{sU[1][19][i][0], sU[1][19][i][1]} : I2[i];
        }
        cd PRE[16], POST[16], T[16], F[16];
        kron2(R, S, PRE);
        kron2(P, Q, POST);
        mm4(C, PRE, T);
        mm4(POST, T, F);
        for (int i = 0; i < 16; i++)
            d_F[q][i] = make_float2((float)F[i].re, (float)F[i].im);
    }
}

// ---------------------------------------------------------------------------
// Fused 4x4 gate sweep (proven scalar fp32 version from round 11)
// ---------------------------------------------------------------------------
__device__ __forceinline__ float2 cmulf(float2 a, float2 b) {
    return make_float2(a.x * b.x - a.y * b.y, a.x * b.y + a.y * b.x);
}
__device__ __forceinline__ float2 cmaddf(float2 a, float2 b, float2 c) {
    return make_float2(fmaf(a.x, b.x, fmaf(-a.y, b.y, c.x)),
                       fmaf(a.x, b.y, fmaf( a.y, b.x, c.y)));
}

__device__ __forceinline__ void apply4(float2* sv, const float2* __restrict__ G,
                                       int lb, int tid) {
    float2 g[16];
    #pragma unroll
    for (int i = 0; i < 16; i++) g[i] = G[i];
    #pragma unroll
    for (int grp = tid; grp < 1024; grp += 256) {
        int low  = grp & ((1 << lb) - 1);
        int base = ((grp >> lb) << (lb + 2)) | low;
        int i1 = base | (1 << lb);
        int i2 = base | (2 << lb);
        int i3 = base | (3 << lb);
        float2 v0 = sv[base], v1 = sv[i1], v2 = sv[i2], v3 = sv[i3];
        float2 o0 = cmaddf(g[3],  v3, cmaddf(g[2],  v2, cmaddf(g[1],  v1, cmulf(g[0],  v0))));
        float2 o1 = cmaddf(g[7],  v3, cmaddf(g[6],  v2, cmaddf(g[5],  v1, cmulf(g[4],  v0))));
        float2 o2 = cmaddf(g[11], v3, cmaddf(g[10], v2, cmaddf(g[9],  v1, cmulf(g[8],  v0))));
        float2 o3 = cmaddf(g[15], v3, cmaddf(g[14], v2, cmaddf(g[13], v1, cmulf(g[12], v0))));
        sv[base] = o0; sv[i1] = o1; sv[i2] = o2; sv[i3] = o3;
    }
}

// Kernel A: tile = bits {0,1} U {10..19}. Fused chains q=0..8
__global__ void __launch_bounds__(256) kA(const float* __restrict__ x) {
    __shared__ float2 sv[4096];
    int tid = threadIdx.x;
    int b   = blockIdx.x >> 8;
    int mid = blockIdx.x & 255;
    const float* xb = x + ((size_t)b << NQ);
    float2* gb = g_state + ((size_t)b << NQ);
    for (int s = tid; s < 4096; s += 256) {
        int H = s >> 2, c2 = s & 3;
        sv[s] = make_float2(xb[(H << 10) | (mid << 2) | c2], 0.0f);
    }
    __syncthreads();
    #pragma unroll
    for (int q = 0; q < 9; q++) { apply4(sv, d_F[q], 10 - q, tid); __syncthreads(); }
    for (int s = tid; s < 4096; s += 256) {
        int H = s >> 2, c2 = s & 3;
        gb[(H << 10) | (mid << 2) | c2] = sv[s];
    }
}

// Kernel B: tile = low bits 0..11. Fused chains q=9..18.
// Epilogue: bf16 hi/lo split of G AND H, K-major (K=2048):
//   G[a,2t]=Re psi[t,a], G[a,2t+1]=Im ;  H[a,2t]=Im, H[a,2t+1]=-Re
__global__ void __launch_bounds__(256) kB() {
    __shared__ float2 sv[4096];
    int tid = threadIdx.x;
    int b   = blockIdx.x >> 8;
    int hib = blockIdx.x & 255;  // t bits 2..9
    float2* gb = g_state + ((size_t)b << NQ) + ((size_t)hib << 12);

    for (int s = tid; s < 4096; s += 256) sv[s] = gb[s];
    __syncthreads();
    #pragma unroll
    for (int q = 9; q < 19; q++) { apply4(sv, d_F[q], 18 - q, tid); __syncthreads(); }

    size_t mb = (size_t)b * (1024 * 1024);  // bf162 units
    int k2 = hib * 4;
    for (int a = tid; a < 1024; a += 256) {
        __nv_bfloat162 gh[4], gl[4], hh[4], hl[4];
        #pragma unroll
        for (int t2 = 0; t2 < 4; t2++) {
            float2 v = sv[(t2 << 10) | a];
            __nv_bfloat162 h = __floats2bfloat162_rn(v.x, v.y);
            float hr = __bfloat162float(__low2bfloat16(h));
            float hi = __bfloat162float(__high2bfloat16(h));
            float lr = v.x - hr, li = v.y - hi;
            __nv_bfloat162 l = __floats2bfloat162_rn(lr, li);
            gh[t2] = h;
            gl[t2] = l;
            // H = (im, -re) of each pair; bf16 negation is exact -> bit-identical
            hh[t2] = __halves2bfloat162(__high2bfloat16(h),
                                        __float2bfloat16(-__bfloat162float(__low2bfloat16(h))));
            hl[t2] = __halves2bfloat162(__high2bfloat16(l),
                                        __float2bfloat16(-__bfloat162float(__low2bfloat16(l))));
        }
        size_t off = mb + (size_t)a * 1024 + k2;
        *(uint4*)&g_Gh[off] = *(uint4*)gh;
        *(uint4*)&g_Gl[off] = *(uint4*)gl;
        *(uint4*)&g_Hh[off] = *(uint4*)hh;
        *(uint4*)&g_Hl[off] = *(uint4*)hl;
    }
}

// ---------------------------------------------------------------------------
// Kernel C: rdm via bf16 mma.sync, 3-term hi/lo split. R11 geometry
// (TPITCH 80, K-chunk 32, 3-stage ring, 512 threads, 4x4 warps of 32x32),
// but H tiles PRELOADED (6-tile stages) instead of PRMT/XOR-derived:
//   Re = G_a G_c^T ; Im = H_a G_c^T
// ---------------------------------------------------------------------------
#define TPITCH 80                       // 64B data + 16B pad: conflict-free ldmatrix
#define TILE_SM (128 * TPITCH)          // 10240 B
#define STAGE_SM (6 * TILE_SM)          // Gh_a, Gl_a, Hh_a, Hl_a, Gh_c, Gl_c = 61440 B
#define NSTAGE 3
#define SMEM_KC (NSTAGE * STAGE_SM)     // 184320 B

__device__ __forceinline__ void kc_load(uint32_t sb, int buf,
                                        const __nv_bfloat16* const* srcs,
                                        int kc, int tid) {
    int row = tid >> 2, c = tid & 3;
    uint32_t dst = sb + buf * STAGE_SM + row * TPITCH + c * 16;
    #pragma unroll
    for (int t = 0; t < 6; t++)
        cpa16(dst + t * TILE_SM, srcs[t] + (size_t)row * 2048 + kc + c * 8);
}

__global__ void __launch_bounds__(512, 1) kC(float2* __restrict__ out) {
    extern __shared__ char smc[];
    uint32_t sb = smem_u32(smc);
    int tid = threadIdx.x, lane = tid & 31, wid = tid >> 5;
    int wm = wid >> 2, wn = wid & 3;

    int z = blockIdx.x;
    int b = z / 36;
    int pair = z - b * 36;
    int bi = 0;
    while (pair >= 8 - bi) { pair -= 8 - bi; bi++; }
    int bj = bi + pair;
    int a0 = bi << 7, c0 = bj << 7;

    size_t mb = (size_t)b * 1024 * 1024;
    const __nv_bfloat16* Gh = (const __nv_bfloat16*)(g_Gh + mb);
    const __nv_bfloat16* Gl = (const __nv_bfloat16*)(g_Gl + mb);
    const __nv_bfloat16* Hh = (const __nv_bfloat16*)(g_Hh + mb);
    const __nv_bfloat16* Hl = (const __nv_bfloat16*)(g_Hl + mb);
    const __nv_bfloat16* srcs[6] = {
        Gh + (size_t)a0 * 2048, Gl + (size_t)a0 * 2048,
        Hh + (size_t)a0 * 2048, Hl + (size_t)a0 * 2048,
        Gh + (size_t)c0 * 2048, Gl + (size_t)c0 * 2048 };

    float accR[2][4][4], accI[2][4][4];
    #pragma unroll
    for (int i = 0; i < 2; i++)
        #pragma unroll
        for (int j = 0; j < 4; j++)
            #pragma unroll
            for (int k = 0; k < 4; k++) { accR[i][j][k] = 0.f; accI[i][j][k] = 0.f; }

    uint32_t loff = (uint32_t)((lane & 15) * TPITCH + (lane >> 4) * 16);

    // prefetch stages 0 and 1 (distance-2 pipeline)
    kc_load(sb, 0, srcs, 0, tid);
    CP_COMMIT();
    kc_load(sb, 1, srcs, 32, tid);
    CP_COMMIT();

    int buf = 0;
    for (int s = 0; s < 64; s++) {
        if (s < 63) CP_WAIT1(); else CP_WAIT0();  // stage s arrived (s+1 may be in flight)
        __syncthreads();  // stage-s data visible to all; buf (s+2)%3 fully consumed
        if (s + 2 < 64) {
            int nbuf = buf + 2; if (nbuf >= NSTAGE) nbuf -= NSTAGE;
            kc_load(sb, nbuf, srcs, (s + 2) * 32, tid);
            CP_COMMIT();
        }

        uint32_t st = sb + buf * STAGE_SM + loff;
        #pragma unroll
        for (int ks = 0; ks < 2; ks++) {
            uint32_t ko = (uint32_t)(ks * 32);
            uint32_t AH[2][4], AL[2][4], HH[2][4], HL[2][4], BH[2][4], BL[2][4];
            #pragma unroll
            for (int mt = 0; mt < 2; mt++) {
                uint32_t ra = st + (wm * 32 + mt * 16) * TPITCH + ko;
                LDM4(AH[mt], ra);
                LDM4(AL[mt], ra + TILE_SM);
                LDM4(HH[mt], ra + 2 * TILE_SM);
                LDM4(HL[mt], ra + 3 * TILE_SM);
            }
            #pragma unroll
            for (int p = 0; p < 2; p++) {
                uint32_t rb = st + 4 * TILE_SM + (wn * 32 + p * 16) * TPITCH + ko;
                LDM4(BH[p], rb);
                LDM4(BL[p], rb + TILE_SM);
            }
            #pragma unroll
            for (int mt = 0; mt < 2; mt++) {
                #pragma unroll
                for (int nt = 0; nt < 4; nt++) {
                    int p = nt >> 1, q = nt & 1;
                    uint32_t b0h = BH[p][q], b1h = BH[p][q + 2];
                    uint32_t b0l = BL[p][q], b1l = BL[p][q + 2];
                    MMA(accR[mt][nt], AH[mt], b0h, b1h);
                    MMA(accR[mt][nt], AH[mt], b0l, b1l);
                    MMA(accR[mt][nt], AL[mt], b0h, b1h);
                    MMA(accI[mt][nt], HH[mt], b0h, b1h);
                    MMA(accI[mt][nt], HH[mt], b0l, b1l);
                    MMA(accI[mt][nt], HL[mt], b0h, b1h);
                }
            }
        }
        if (++buf >= NSTAGE) buf = 0;
    }

    // epilogue: direct stores + conjugate-transposed mirror
    float2* ob = out + ((size_t)b << 20);
    int rg = a0 + wm * 32 + (lane >> 2);
    int cg = c0 + wn * 32 + 2 * (lane & 3);
    #pragma unroll
    for (int mt = 0; mt < 2; mt++) {
        #pragma unroll
        for (int nt = 0; nt < 4; nt++) {
            int r = rg + mt * 16;
            int c = cg + nt * 8;
            float* R = accR[mt][nt];
            float* I = accI[mt][nt];
            *(float4*)&ob[((size_t)r << 10) + c]       = make_float4(R[0], I[0], R[1], I[1]);
            *(float4*)&ob[((size_t)(r + 8) << 10) + c] = make_float4(R[2], I[2], R[3], I[3]);
            if (bi != bj) {
                ob[((size_t)c << 10) + r]           = make_float2(R[0], -I[0]);
                ob[((size_t)(c + 1) << 10) + r]     = make_float2(R[1], -I[1]);
                ob[((size_t)c << 10) + r + 8]       = make_float2(R[2], -I[2]);
                ob[((size_t)(c + 1) << 10) + r + 8] = make_float2(R[3], -I[3]);
            }
        }
    }
}

// ---------------------------------------------------------------------------
extern "C" void kernel_launch(void* const* d_in, const int* in_sizes, int n_in,
                              void* d_out, int out_size) {
    const float* x = (const float*)d_in[0];
    const float* w = (const float*)d_in[1];
    (void)in_sizes; (void)n_in; (void)out_size;

    cudaFuncSetAttribute(kC, cudaFuncAttributeMaxDynamicSharedMemorySize, SMEM_KC);

    kprep<<<1, 64>>>(w);
    kA<<<BATCH * 256, 256>>>(x);
    kB<<<BATCH * 256, 256>>>();
    kC<<<BATCH * 36, 512, SMEM_KC>>>((float2*)d_out);
}

// round 17
// speedup vs baseline: 1.0916x; 1.0916x over previous
#include <cuda_runtime.h>
#include <cuda_bf16.h>
#include <cstdint>

#define BATCH 4
#define NQ 20
#define DIM (1u << NQ)

__device__ float2 g_state[BATCH * DIM];                 // 32 MB (kA -> kB)
__device__ __nv_bfloat162 g_Gh[(size_t)BATCH * 1024 * 1024];  // 16 MB: bf16-hi of G (K=2048)
__device__ __nv_bfloat162 g_Gl[(size_t)BATCH * 1024 * 1024];  // 16 MB: residual lo

__device__ float2 d_F[19][16];   // fused 4x4 chain gates (row-major, i=2*s_q+s_{q+1})

// ---------------------------------------------------------------------------
// helpers
// ---------------------------------------------------------------------------
__device__ __forceinline__ uint32_t smem_u32(const void* p) {
    uint32_t a;
    asm("{ .reg .u64 t; cvta.to.shared.u64 t, %1; cvt.u32.u64 %0, t; }" : "=r"(a) : "l"(p));
    return a;
}
__device__ __forceinline__ void cpa16(uint32_t dst, const void* src) {
    asm volatile("cp.async.cg.shared.global [%0], [%1], 16;" :: "r"(dst), "l"(src));
}
#define CP_COMMIT() asm volatile("cp.async.commit_group;" ::: "memory")
#define CP_WAIT0()  asm volatile("cp.async.wait_group 0;" ::: "memory")
#define CP_WAIT1()  asm volatile("cp.async.wait_group 1;" ::: "memory")

#define LDM4(r, addr) \
    asm volatile("ldmatrix.sync.aligned.m8n8.x4.shared.b16 {%0,%1,%2,%3}, [%4];" \
        : "=r"((r)[0]), "=r"((r)[1]), "=r"((r)[2]), "=r"((r)[3]) : "r"(addr))

#define MMA(d, a, b0, b1) \
    asm volatile("mma.sync.aligned.m16n8k16.row.col.f32.bf16.bf16.f32 " \
        "{%0,%1,%2,%3}, {%4,%5,%6,%7}, {%8,%9}, {%0,%1,%2,%3};" \
        : "+f"((d)[0]), "+f"((d)[1]), "+f"((d)[2]), "+f"((d)[3]) \
        : "r"((a)[0]), "r"((a)[1]), "r"((a)[2]), "r"((a)[3]), "r"(b0), "r"(b1))

// ---------------------------------------------------------------------------
// Gate precompute: fuse ALL singles into the 19 chain gates (fp64).
//   F(q,q+1) = (U2(q) (x) Q) * C(q,q+1) * (R (x) U1(q+1))
//   R = U1(0) for q==0 else I ;  Q = U2(19) for q==18 else I
// ---------------------------------------------------------------------------
struct cd { double re, im; };
__device__ __forceinline__ cd cmuld(cd a, cd b) {
    return {a.re * b.re - a.im * b.im, a.re * b.im + a.im * b.re};
}
__device__ __forceinline__ cd caddd(cd a, cd b) { return {a.re + b.re, a.im + b.im}; }
__device__ void mm2(const cd* A, const cd* B, cd* C) {
    C[0] = caddd(cmuld(A[0], B[0]), cmuld(A[1], B[2]));
    C[1] = caddd(cmuld(A[0], B[1]), cmuld(A[1], B[3]));
    C[2] = caddd(cmuld(A[2], B[0]), cmuld(A[3], B[2]));
    C[3] = caddd(cmuld(A[2], B[1]), cmuld(A[3], B[3]));
}
__device__ void mm4(const cd* A, const cd* B, cd* C) {
    for (int i = 0; i < 4; i++)
        for (int j = 0; j < 4; j++) {
            cd s = {0, 0};
            for (int k = 0; k < 4; k++) s = caddd(s, cmuld(A[i * 4 + k], B[k * 4 + j]));
            C[i * 4 + j] = s;
        }
}
__device__ void kron2(const cd* A, const cd* B, cd* K) {
    for (int i0 = 0; i0 < 2; i0++)
        for (int i1 = 0; i1 < 2; i1++)
            for (int j0 = 0; j0 < 2; j0++)
                for (int j1 = 0; j1 < 2; j1++)
                    K[(2 * i0 + i1) * 4 + (2 * j0 + j1)] =
                        cmuld(A[i0 * 2 + j0], B[i1 * 2 + j1]);
}

__global__ void kprep(const float* __restrict__ w) {
    __shared__ double sU[2][20][4][2];  // [layer][q][elem][re/im]
    int t = threadIdx.x;
    const double WM = 0.6324555320336759;  // sqrt(2)/sqrt(5)
    if (t < 40) {
        int q = t % 20;
        int layer = t < 20 ? 0 : 1;
        int base = layer == 0 ? 3 * q : (117 + 3 * q);
        double ax = (double)w[base]     * WM * 0.5;
        double ay = (double)w[base + 1] * WM * 0.5;
        double az = (double)w[base + 2] * WM * 0.5;
        double cx = cos(ax), sx = sin(ax);
        double cy = cos(ay), sy = sin(ay);
        double cz = cos(az), sz = sin(az);
        cd RX[4] = {{cx, 0}, {0, -sx}, {0, -sx}, {cx, 0}};
        cd RY[4] = {{cy, 0}, {-sy, 0}, {sy, 0}, {cy, 0}};
        cd RYX[4]; mm2(RY, RX, RYX);
        cd z0 = {cz, -sz}, z1 = {cz, sz};
        cd U[4] = {cmuld(z0, RYX[0]), cmuld(z0, RYX[1]),
                   cmuld(z1, RYX[2]), cmuld(z1, RYX[3])};
        for (int i = 0; i < 4; i++) { sU[layer][q][i][0] = U[i].re; sU[layer][q][i][1] = U[i].im; }
    }
    __syncthreads();
    if (t < 19) {
        int q = t;
        int base = 60 + 3 * q;
        double ax = (double)w[base]     * WM * 0.5;
        double ay = (double)w[base + 1] * WM * 0.5;
        double az = (double)w[base + 2] * WM * 0.5;
        double cx = cos(ax), sx = sin(ax);
        double cy = cos(ay), sy = sin(ay);
        double cz = cos(az), sz = sin(az);
        cd RXXb[4] = {{cx, 0}, {0, -sx}, {0, -sx}, {cx, 0}};
        cd RYY0[4] = {{cy, 0}, {0,  sy}, {0,  sy}, {cy, 0}};
        cd RYY1[4] = {{cy, 0}, {0, -sy}, {0, -sy}, {cy, 0}};
        cd M0[4]; mm2(RYY0, RXXb, M0);
        cd M1[4]; mm2(RYY1, RXXb, M1);
        cd p0 = {cz, -sz}, p1 = {cz, sz};
        cd g00[4], g01[4];
        for (int i = 0; i < 4; i++) { g00[i] = cmuld(p0, M0[i]); g01[i] = cmuld(p1, M1[i]); }
        cd C[16];
        for (int i = 0; i < 16; i++) C[i] = {0, 0};
        C[0 * 4 + 0] = g00[0]; C[0 * 4 + 3] = g00[1];
        C[3 * 4 + 0] = g00[2]; C[3 * 4 + 3] = g00[3];
        C[1 * 4 + 1] = g01[0]; C[1 * 4 + 2] = g01[1];
        C[2 * 4 + 1] = g01[2]; C[2 * 4 + 2] = g01[3];
        cd I2[4] = {{1, 0}, {0, 0}, {0, 0}, {1, 0}};
        cd R[4], S[4], P[4], Q[4];
        for (int i = 0; i < 4; i++) {
            R[i] = (q == 0)  ? cd{sU[0][0][i][0],  sU[0][0][i][1]}  : I2[i];
            S[i] = cd{sU[0][q + 1][i][0], sU[0][q + 1][i][1]};
            P[i] = cd{sU[1][q][i][0],     sU[1][q][i][1]};
            Q[i] = (q == 18) ? cd{sU[1][19][i][0], sU[1][19][i][1]} : I2[i];
        }
        cd PRE[16], POST[16], T[16], F[16];
        kron2(R, S, PRE);
        kron2(P, Q, POST);
        mm4(C, PRE, T);
        mm4(POST, T, F);
        for (int i = 0; i < 16; i++)
            d_F[q][i] = make_float2((float)F[i].re, (float)F[i].im);
    }
}

// ---------------------------------------------------------------------------
// Gate sweeps
// ---------------------------------------------------------------------------
__device__ __forceinline__ float2 cmulf(float2 a, float2 b) {
    return make_float2(a.x * b.x - a.y * b.y, a.x * b.y + a.y * b.x);
}
__device__ __forceinline__ float2 cmaddf(float2 a, float2 b, float2 c) {
    return make_float2(fmaf(a.x, b.x, fmaf(-a.y, b.y, c.x)),
                       fmaf(a.x, b.y, fmaf( a.y, b.x, c.y)));
}

// single 4x4 gate on local bits (lb+1, lb) — proven R11 version
__device__ __forceinline__ void apply4(float2* sv, const float2* __restrict__ G,
                                       int lb, int tid) {
    float2 g[16];
    #pragma unroll
    for (int i = 0; i < 16; i++) g[i] = G[i];
    #pragma unroll
    for (int grp = tid; grp < 1024; grp += 256) {
        int low  = grp & ((1 << lb) - 1);
        int base = ((grp >> lb) << (lb + 2)) | low;
        int i1 = base | (1 << lb);
        int i2 = base | (2 << lb);
        int i3 = base | (3 << lb);
        float2 v0 = sv[base], v1 = sv[i1], v2 = sv[i2], v3 = sv[i3];
        float2 o0 = cmaddf(g[3],  v3, cmaddf(g[2],  v2, cmaddf(g[1],  v1, cmulf(g[0],  v0))));
        float2 o1 = cmaddf(g[7],  v3, cmaddf(g[6],  v2, cmaddf(g[5],  v1, cmulf(g[4],  v0))));
        float2 o2 = cmaddf(g[11], v3, cmaddf(g[10], v2, cmaddf(g[9],  v1, cmulf(g[8],  v0))));
        float2 o3 = cmaddf(g[15], v3, cmaddf(g[14], v2, cmaddf(g[13], v1, cmulf(g[12], v0))));
        sv[base] = o0; sv[i1] = o1; sv[i2] = o2; sv[i3] = o3;
    }
}

// Two consecutive chain gates applied on an 8-amp register block.
// G0 = F_q acts on bits (lb+2, lb+1); G1 = F_{q+1} acts on bits (lb+1, lb).
// Amp index k = 4*b2 + 2*b1 + b0. Same arithmetic order as two apply4 passes.
__device__ __forceinline__ void applyPair(float2* sv,
                                          const float2* __restrict__ G0,
                                          const float2* __restrict__ G1,
                                          int lb, int tid) {
    float2 g0[16], g1[16];
    #pragma unroll
    for (int i = 0; i < 16; i++) { g0[i] = G0[i]; g1[i] = G1[i]; }
    #pragma unroll
    for (int it = 0; it < 2; it++) {
        int grp  = tid + it * 256;                 // 512 groups of 8 amps
        int low  = grp & ((1 << lb) - 1);
        int base = ((grp >> lb) << (lb + 3)) | low;
        float2 v[8];
        #pragma unroll
        for (int k = 0; k < 8; k++) v[k] = sv[base + (k << lb)];
        // F_q on (b2,b1), b0 fixed: input u_j = v[2j + b0]
        float2 w[8];
        #pragma unroll
        for (int b0 = 0; b0 < 2; b0++) {
            #pragma unroll
            for (int r = 0; r < 4; r++) {
                w[2 * r + b0] =
                    cmaddf(g0[4 * r + 3], v[6 + b0],
                    cmaddf(g0[4 * r + 2], v[4 + b0],
                    cmaddf(g0[4 * r + 1], v[2 + b0],
                    cmulf (g0[4 * r],     v[b0]))));
            }
        }
        // F_{q+1} on (b1,b0), b2 fixed: input u_j = w[4*b2 + j]
        #pragma unroll
        for (int b2 = 0; b2 < 2; b2++) {
            #pragma unroll
            for (int r = 0; r < 4; r++) {
                float2 o =
                    cmaddf(g1[4 * r + 3], w[4 * b2 + 3],
                    cmaddf(g1[4 * r + 2], w[4 * b2 + 2],
                    cmaddf(g1[4 * r + 1], w[4 * b2 + 1],
                    cmulf (g1[4 * r],     w[4 * b2]))));
                sv[base + ((4 * b2 + r) << lb)] = o;
            }
        }
    }
}

// Kernel A: tile = bits {0,1} U {10..19}. Chains q=0..8 as 4 pairs + single F8.
// Wire q sits at local bit 11-q; pair (q,q+1) uses lb = 9-q.
__global__ void __launch_bounds__(256) kA(const float* __restrict__ x) {
    __shared__ float2 sv[4096];
    int tid = threadIdx.x;
    int b   = blockIdx.x >> 8;
    int mid = blockIdx.x & 255;
    const float* xb = x + ((size_t)b << NQ);
    float2* gb = g_state + ((size_t)b << NQ);
    for (int s = tid; s < 4096; s += 256) {
        int H = s >> 2, c2 = s & 3;
        sv[s] = make_float2(xb[(H << 10) | (mid << 2) | c2], 0.0f);
    }
    __syncthreads();
    applyPair(sv, d_F[0], d_F[1], 9, tid); __syncthreads();
    applyPair(sv, d_F[2], d_F[3], 7, tid); __syncthreads();
    applyPair(sv, d_F[4], d_F[5], 5, tid); __syncthreads();
    applyPair(sv, d_F[6], d_F[7], 3, tid); __syncthreads();
    apply4(sv, d_F[8], 2, tid); __syncthreads();
    for (int s = tid; s < 4096; s += 256) {
        int H = s >> 2, c2 = s & 3;
        gb[(H << 10) | (mid << 2) | c2] = sv[s];
    }
}

// Kernel B: tile = low bits 0..11. Chains q=9..18 as 5 pairs.
// Wire q sits at local bit 19-q; pair (q,q+1) uses lb = 17-q.
// Epilogue: bf16 hi/lo split of G, K-major (K=2048).
__global__ void __launch_bounds__(256) kB() {
    __shared__ float2 sv[4096];
    int tid = threadIdx.x;
    int b   = blockIdx.x >> 8;
    int hib = blockIdx.x & 255;  // t bits 2..9
    float2* gb = g_state + ((size_t)b << NQ) + ((size_t)hib << 12);

    for (int s = tid; s < 4096; s += 256) sv[s] = gb[s];
    __syncthreads();
    applyPair(sv, d_F[9],  d_F[10], 8, tid); __syncthreads();
    applyPair(sv, d_F[11], d_F[12], 6, tid); __syncthreads();
    applyPair(sv, d_F[13], d_F[14], 4, tid); __syncthreads();
    applyPair(sv, d_F[15], d_F[16], 2, tid); __syncthreads();
    applyPair(sv, d_F[17], d_F[18], 0, tid); __syncthreads();

    size_t mb = (size_t)b * (1024 * 1024);  // bf162 units
    int k2 = hib * 4;
    for (int a = tid; a < 1024; a += 256) {
        __nv_bfloat162 gh[4], gl[4];
        #pragma unroll
        for (int t2 = 0; t2 < 4; t2++) {
            float2 v = sv[(t2 << 10) | a];
            __nv_bfloat162 h = __floats2bfloat162_rn(v.x, v.y);
            float hr = __bfloat162float(__low2bfloat16(h));
            float hi = __bfloat162float(__high2bfloat16(h));
            gh[t2] = h;
            gl[t2] = __floats2bfloat162_rn(v.x - hr, v.y - hi);
        }
        size_t off = mb + (size_t)a * 1024 + k2;
        *(uint4*)&g_Gh[off] = *(uint4*)gh;
        *(uint4*)&g_Gl[off] = *(uint4*)gl;
    }
}

// ---------------------------------------------------------------------------
// Kernel C: rdm via bf16 mma.sync, 3-term hi/lo split.  (BYTE-IDENTICAL to
// the proven 193us round-11 version: TPITCH 80, K-chunk 32, 3-stage ring,
// 512 threads, 4x4 warps of 32x32 tiles, H derived via PRMT/XOR.)
//   Re = G_a G_c^T ; Im = H_a G_c^T, H reg = halfword_swap(G reg) ^ 0x80000000
// ---------------------------------------------------------------------------
#define TPITCH 80                       // 64B data + 16B pad: conflict-free ldmatrix
#define TILE_SM (128 * TPITCH)          // 10240 B
#define STAGE_SM (4 * TILE_SM)          // Gh_a, Gl_a, Gh_c, Gl_c = 40960 B
#define NSTAGE 3
#define SMEM_KC (NSTAGE * STAGE_SM)     // 122880 B

__device__ __forceinline__ void kc_load(uint32_t sb, int buf,
                                        const __nv_bfloat16* const* srcs,
                                        int kc, int tid) {
    int row = tid >> 2, c = tid & 3;
    uint32_t dst = sb + buf * STAGE_SM + row * TPITCH + c * 16;
    #pragma unroll
    for (int t = 0; t < 4; t++)
        cpa16(dst + t * TILE_SM, srcs[t] + (size_t)row * 2048 + kc + c * 8);
}

__global__ void __launch_bounds__(512, 1) kC(float2* __restrict__ out) {
    extern __shared__ char smc[];
    uint32_t sb = smem_u32(smc);
    int tid = threadIdx.x, lane = tid & 31, wid = tid >> 5;
    int wm = wid >> 2, wn = wid & 3;

    int z = blockIdx.x;
    int b = z / 36;
    int pair = z - b * 36;
    int bi = 0;
    while (pair >= 8 - bi) { pair -= 8 - bi; bi++; }
    int bj = bi + pair;
    int a0 = bi << 7, c0 = bj << 7;

    const __nv_bfloat16* Gh = (const __nv_bfloat16*)(g_Gh + (size_t)b * 1024 * 1024);
    const __nv_bfloat16* Gl = (const __nv_bfloat16*)(g_Gl + (size_t)b * 1024 * 1024);
    const __nv_bfloat16* srcs[4] = {
        Gh + (size_t)a0 * 2048, Gl + (size_t)a0 * 2048,
        Gh + (size_t)c0 * 2048, Gl + (size_t)c0 * 2048 };

    float accR[2][4][4], accI[2][4][4];
    #pragma unroll
    for (int i = 0; i < 2; i++)
        #pragma unroll
        for (int j = 0; j < 4; j++)
            #pragma unroll
            for (int k = 0; k < 4; k++) { accR[i][j][k] = 0.f; accI[i][j][k] = 0.f; }

    uint32_t loff = (uint32_t)((lane & 15) * TPITCH + (lane >> 4) * 16);

    // prefetch stages 0 and 1 (distance-2 pipeline)
    kc_load(sb, 0, srcs, 0, tid);
    CP_COMMIT();
    kc_load(sb, 1, srcs, 32, tid);
    CP_COMMIT();

    int buf = 0;
    for (int s = 0; s < 64; s++) {
        if (s < 63) CP_WAIT1(); else CP_WAIT0();  // stage s arrived (s+1 may be in flight)
        __syncthreads();  // stage-s data visible to all; buf (s+2)%3 fully consumed
        if (s + 2 < 64) {
            int nbuf = buf + 2; if (nbuf >= NSTAGE) nbuf -= NSTAGE;
            kc_load(sb, nbuf, srcs, (s + 2) * 32, tid);
            CP_COMMIT();
        }

        uint32_t st = sb + buf * STAGE_SM + loff;
        #pragma unroll
        for (int ks = 0; ks < 2; ks++) {
            uint32_t ko = (uint32_t)(ks * 32);
            uint32_t AH[2][4], AL[2][4], BH[2][4], BL[2][4];
            #pragma unroll
            for (int mt = 0; mt < 2; mt++) {
                uint32_t ra = st + (wm * 32 + mt * 16) * TPITCH + ko;
                LDM4(AH[mt], ra);
                LDM4(AL[mt], ra + TILE_SM);
            }
            #pragma unroll
            for (int p = 0; p < 2; p++) {
                uint32_t rb = st + 2 * TILE_SM + (wn * 32 + p * 16) * TPITCH + ko;
                LDM4(BH[p], rb);
                LDM4(BL[p], rb + TILE_SM);
            }
            #pragma unroll
            for (int mt = 0; mt < 2; mt++) {
                uint32_t HH[4], HL[4];
                #pragma unroll
                for (int i = 0; i < 4; i++) {
                    HH[i] = __byte_perm(AH[mt][i], AH[mt][i], 0x1032) ^ 0x80000000u;
                    HL[i] = __byte_perm(AL[mt][i], AL[mt][i], 0x1032) ^ 0x80000000u;
                }
                #pragma unroll
                for (int nt = 0; nt < 4; nt++) {
                    int p = nt >> 1, q = nt & 1;
                    uint32_t b0h = BH[p][q], b1h = BH[p][q + 2];
                    uint32_t b0l = BL[p][q], b1l = BL[p][q + 2];
                    MMA(accR[mt][nt], AH[mt], b0h, b1h);
                    MMA(accR[mt][nt], AH[mt], b0l, b1l);
                    MMA(accR[mt][nt], AL[mt], b0h, b1h);
                    MMA(accI[mt][nt], HH, b0h, b1h);
                    MMA(accI[mt][nt], HH, b0l, b1l);
                    MMA(accI[mt][nt], HL, b0h, b1h);
                }
            }
        }
        if (++buf >= NSTAGE) buf = 0;
    }

    // epilogue: direct stores + conjugate-transposed mirror
    float2* ob = out + ((size_t)b << 20);
    int rg = a0 + wm * 32 + (lane >> 2);
    int cg = c0 + wn * 32 + 2 * (lane & 3);
    #pragma unroll
    for (int mt = 0; mt < 2; mt++) {
        #pragma unroll
        for (int nt = 0; nt < 4; nt++) {
            int r = rg + mt * 16;
            int c = cg + nt * 8;
            float* R = accR[mt][nt];
            float* I = accI[mt][nt];
            *(float4*)&ob[((size_t)r << 10) + c]       = make_float4(R[0], I[0], R[1], I[1]);
            *(float4*)&ob[((size_t)(r + 8) << 10) + c] = make_float4(R[2], I[2], R[3], I[3]);
            if (bi != bj) {
                ob[((size_t)c << 10) + r]           = make_float2(R[0], -I[0]);
                ob[((size_t)(c + 1) << 10) + r]     = make_float2(R[1], -I[1]);
                ob[((size_t)c << 10) + r + 8]       = make_float2(R[2], -I[2]);
                ob[((size_t)(c + 1) << 10) + r + 8] = make_float2(R[3], -I[3]);
            }
        }
    }
}

// ---------------------------------------------------------------------------
extern "C" void kernel_launch(void* const* d_in, const int* in_sizes, int n_in,
                              void* d_out, int out_size) {
    const float* x = (const float*)d_in[0];
    const float* w = (const float*)d_in[1];
    (void)in_sizes; (void)n_in; (void)out_size;

    cudaFuncSetAttribute(kC, cudaFuncAttributeMaxDynamicSharedMemorySize, SMEM_KC);

    kprep<<<1, 64>>>(w);
    kA<<<BATCH * 256, 256>>>(x);
    kB<<<BATCH * 256, 256>>>();
    kC<<<BATCH * 36, 512, SMEM_KC>>>((float2*)d_out);
}